// round 11
// baseline (speedup 1.0000x reference)
#include <cuda_runtime.h>
#include <cuda_bf16.h>
#include <stdint.h>

#define BB 4096
#define DD 1024
#define RR 256
#define NCTA 128
#define NTHR 512

#define K_W1 1.3512071919596578
#define K_W0 (-1.7024143839193153)
#define K_C1f ((float)(K_W1 * 0.5))
#define K_C2f ((float)((K_W0 + K_W1) * 0.5))
#define K_DT 0.01f

// -------- device-global scratch (no runtime allocation) --------
__device__ __align__(1024) unsigned char g_Ub[16 * 32768];   // U bf16: 16 k-chunks [256n x 64k] SW128
__device__ __align__(1024) unsigned char g_Wb[64 * 8192];    // W bf16: 16 n-chunks x 4 k-tiles [64n x 64k] SW128
__device__ __align__(1024) float g_vf[(size_t)BB * DD];      // v fp32 master

// -------- helpers --------
__device__ __forceinline__ uint32_t swz(uint32_t o) { return o ^ ((o >> 3) & 0x70); }
__device__ __forceinline__ uint32_t s2u(const void* p) {
    uint32_t a; asm("{ .reg .u64 t; cvta.to.shared.u64 t, %1; cvt.u32.u64 %0, t; }" : "=r"(a) : "l"(p)); return a;
}
__device__ __forceinline__ uint32_t bf2u(__nv_bfloat162 b) { return *reinterpret_cast<uint32_t*>(&b); }
__device__ __forceinline__ void mb_init(uint32_t a, uint32_t c) {
    asm volatile("mbarrier.init.shared.b64 [%0], %1;" :: "r"(a), "r"(c) : "memory");
}
__device__ __forceinline__ void mb_expect(uint32_t a, uint32_t b) {
    asm volatile("mbarrier.arrive.expect_tx.shared.b64 _, [%0], %1;" :: "r"(a), "r"(b) : "memory");
}
__device__ __forceinline__ void mb_wait(uint32_t a, uint32_t p) {
    asm volatile("{\n\t.reg .pred P;\n\tLW%=:\n\t"
        "mbarrier.try_wait.parity.acquire.cta.shared::cta.b64 P, [%0], %1, 0x989680;\n\t"
        "@P bra LD%=;\n\tbra LW%=;\n\tLD%=:\n\t}" :: "r"(a), "r"(p) : "memory");
}
__device__ __forceinline__ void bulkcp(uint32_t d, const void* s, uint32_t n, uint32_t mb) {
    asm volatile("cp.async.bulk.shared::cluster.global.mbarrier::complete_tx::bytes [%0], [%1], %2, [%3];"
                 :: "r"(d), "l"(s), "r"(n), "r"(mb) : "memory");
}
__device__ __forceinline__ void fence_async_sh() { asm volatile("fence.proxy.async.shared::cta;" ::: "memory"); }
__device__ __forceinline__ void nbar_sync(int id, int cnt) {
    asm volatile("bar.sync %0, %1;" :: "r"(id), "r"(cnt) : "memory");
}
__device__ __forceinline__ void nbar_arrive(int id, int cnt) {
    asm volatile("bar.arrive %0, %1;" :: "r"(id), "r"(cnt) : "memory");
}
__device__ __forceinline__ void ldsm4(uint32_t* r, uint32_t a) {
    asm volatile("ldmatrix.sync.aligned.m8n8.x4.shared.b16 {%0,%1,%2,%3}, [%4];"
                 : "=r"(r[0]), "=r"(r[1]), "=r"(r[2]), "=r"(r[3]) : "r"(a));
}
__device__ __forceinline__ void lds64(uint32_t* r, uint32_t a) {
    asm volatile("ld.shared.v2.u32 {%0,%1}, [%2];" : "=r"(r[0]), "=r"(r[1]) : "r"(a));
}
__device__ __forceinline__ void mma16816(float* c, const uint32_t* a, const uint32_t* b) {
    asm volatile("mma.sync.aligned.m16n8k16.row.col.f32.bf16.bf16.f32 "
        "{%0,%1,%2,%3}, {%4,%5,%6,%7}, {%8,%9}, {%0,%1,%2,%3};"
        : "+f"(c[0]), "+f"(c[1]), "+f"(c[2]), "+f"(c[3])
        : "r"(a[0]), "r"(a[1]), "r"(a[2]), "r"(a[3]), "r"(b[0]), "r"(b[1]));
}
__device__ __forceinline__ void sts32(uint32_t a, uint32_t v) {
    asm volatile("st.shared.b32 [%0], %1;" :: "r"(a), "r"(v) : "memory");
}
__device__ __forceinline__ void sts64(uint32_t a, uint32_t v0, uint32_t v1) {
    asm volatile("st.shared.v2.u32 [%0], {%1, %2};" :: "r"(a), "r"(v0), "r"(v1) : "memory");
}
__device__ __forceinline__ const unsigned char* chunk_src(int g) {
    int l = g & 31;
    return (l < 16) ? (g_Ub + (size_t)l * 32768) : (g_Wb + (size_t)(l - 16) * 32768);
}

// -------- prologue: fp32 -> bf16 SW128 tiles in gmem --------
__global__ void prep_uw_kernel(const float* __restrict__ U, const float* __restrict__ W) {
    int idx = blockIdx.x * blockDim.x + threadIdx.x;       // 262144
    if (idx < 131072) {
        int kc = idx >> 13, rem = idx & 8191, r = rem >> 5, j = rem & 31;
        float2 f = *(const float2*)(U + (size_t)r * DD + kc * 64 + j * 2);
        *(uint32_t*)(g_Ub + kc * 32768 + swz((uint32_t)(r * 128 + j * 4))) = bf2u(__float22bfloat162_rn(f));
    } else {
        int i2 = idx - 131072;
        int t = i2 >> 11, rem = i2 & 2047, dr = rem >> 5, j = rem & 31;
        int nc = t >> 2, kt = t & 3;
        float2 f = *(const float2*)(W + (size_t)(nc * 64 + dr) * RR + kt * 64 + j * 2);
        *(uint32_t*)(g_Wb + t * 8192 + swz((uint32_t)(dr * 128 + j * 4))) = bf2u(__float22bfloat162_rn(f));
    }
}

// -------- main fused integrator: 8 GEMM warps + 8 elementwise warps --------
__global__ __launch_bounds__(NTHR, 1)
void yoshida_mma8_kernel(const float* __restrict__ x, const float* __restrict__ v,
                         const float* __restrict__ force, float* __restrict__ out) {
    extern __shared__ unsigned char dsm[];
    unsigned char* basep = (unsigned char*)(((uintptr_t)dsm + 1023u) & ~(uintptr_t)1023u);
    const uint32_t base = s2u(basep);
    const uint32_t SV   = base;                 // 64KB resident v bf16: 16 tiles [32 x 64] SW128
    const uint32_t RING = base + 65536u;        // 4 x 32KB unified U/W chunk ring
    const uint32_t H2   = base + 196608u;       // 4 x 4KB h^2 tiles [32 x 64] bf16 SW128
    const uint32_t SGu  = base + 212992u;       // sGamma bf16 [32 rows][260 cols] pitch 520B
    const uint32_t BARS = base + 230400u;       // mbars full[4]

    const int tid = threadIdx.x, wid = tid >> 5, lid = tid & 31;
    const bool isG = (wid < 8);
    const int row0 = blockIdx.x * 32;

    // G-warp indices
    const int p  = (wid >> 1) & 3;             // GEMM2 pair id (buffer owner)
    const int pw = wid & 1;                    // GEMM2 N 32-half within chunk
    const uint32_t arow0 = (uint32_t)((lid & 15) * 128 + ((lid >> 4) << 4));
    const uint32_t arow1 = arow0 + 2048u;      // rows +16
    const uint32_t brow  = (uint32_t)(((lid & 7) + ((lid >> 4) << 3)) * 128 + (((lid >> 3) & 1) << 4));
    const int hr = lid >> 2, hc2 = (lid & 3) * 2;

    // E-warp indices
    const int et = tid & 255;
    const int er = et >> 3, ec = et & 7;
    const size_t egrow = (size_t)(row0 + er) * DD;

    if (tid == 0) {
        #pragma unroll
        for (int i = 0; i < 4; ++i) mb_init(BARS + 8u * i, 1);
        fence_async_sh();
        #pragma unroll
        for (int c = 0; c < 4; ++c) {
            mb_expect(BARS + 8u * c, 32768u);
            bulkcp(RING + (uint32_t)c * 32768u, chunk_src(c), 32768u, BARS + 8u * c);
        }
    }

    // resident sV init: bf16(v) pre-swizzled (all threads)
    for (int i = tid; i < 8192; i += NTHR) {
        int row = i >> 8, rem = i & 255, kc = rem >> 4, jj = rem & 15;
        float4 f = *(const float4*)(v + (size_t)(row0 + row) * DD + kc * 64 + jj * 4);
        sts64(SV + (uint32_t)kc * 4096u + swz((uint32_t)(row * 128 + jj * 8)),
              bf2u(__float22bfloat162_rn(make_float2(f.x, f.y))),
              bf2u(__float22bfloat162_rn(make_float2(f.z, f.w))));
    }
    __syncthreads();
    if (!isG) {                                // pre-arm consumed + sv_ready
        nbar_arrive(7, 512);
        nbar_arrive(8, 512);
    }

    const float dctab[3] = { (float)K_W1 * K_DT, (float)K_W0 * K_DT, (float)K_W1 * K_DT };

    for (int step = 0; step < 3; ++step) {
        if (isG) {
            // ===== GEMM1: h[32 x 256] = sV @ U^T; warp = 32M x 32N, serial 16 chunks =====
            float acc1[8][4];
            #pragma unroll
            for (int t = 0; t < 8; ++t)
                #pragma unroll
                for (int j = 0; j < 4; ++j) acc1[t][j] = 0.f;

            for (int kc = 0; kc < 16; ++kc) {
                if (kc == 12) nbar_sync(8, 512);          // SV tiles 12-15: prev-step ew g3 done
                const int g = step * 32 + kc;
                const int b = kc & 3;
                mb_wait(BARS + 8u * b, (uint32_t)((kc >> 2) & 1));
                const uint32_t Ab = SV + (uint32_t)kc * 4096u;
                const uint32_t Bb = RING + (uint32_t)b * 32768u;
                #pragma unroll
                for (int ks = 0; ks < 4; ++ks) {
                    uint32_t a0[4], a1[4];
                    ldsm4(a0, Ab + swz(arow0 + ks * 32));
                    ldsm4(a1, Ab + swz(arow1 + ks * 32));
                    #pragma unroll
                    for (int h = 0; h < 2; ++h) {
                        uint32_t bb[4];
                        ldsm4(bb, Bb + swz(brow + (uint32_t)((wid * 32 + h * 16) * 128) + ks * 32));
                        mma16816(acc1[h * 2],     a0, bb);
                        mma16816(acc1[h * 2 + 1], a0, bb + 2);
                        mma16816(acc1[4 + h * 2],     a1, bb);
                        mma16816(acc1[4 + h * 2 + 1], a1, bb + 2);
                    }
                }
                const int bid = 2 + b;
                if (wid == 7) {
                    nbar_sync(bid, 256);                  // all 8 G warps consumed
                    if (lid == 0 && g + 4 < 96) {
                        mb_expect(BARS + 8u * b, 32768u);
                        bulkcp(RING + (uint32_t)b * 32768u, chunk_src(g + 4), 32768u, BARS + 8u * b);
                    }
                } else {
                    nbar_arrive(bid, 256);
                }
            }

            // ---- h^2 -> H2 bf16 tiles (warp owns 32 cols, all 32 rows) ----
            {
                const uint32_t ht = H2 + (uint32_t)(wid >> 1) * 4096u;
                #pragma unroll
                for (int t = 0; t < 8; ++t) {
                    const int mr = t >> 2, h = (t >> 1) & 1, n8 = t & 1;
                    const uint32_t koff = (uint32_t)(((wid & 1) * 32 + h * 16 + n8 * 8 + hc2) * 2);
                    float c0 = acc1[t][0], c1 = acc1[t][1], c2 = acc1[t][2], c3 = acc1[t][3];
                    sts32(ht + swz((uint32_t)((mr * 16 + hr) * 128) + koff),
                          bf2u(__float22bfloat162_rn(make_float2(c0 * c0, c1 * c1))));
                    sts32(ht + swz((uint32_t)((mr * 16 + hr + 8) * 128) + koff),
                          bf2u(__float22bfloat162_rn(make_float2(c2 * c2, c3 * c3))));
                }
            }
            nbar_sync(1, 256);                            // H2 visible to all G warps

            // ===== GEMM2: 4 groups; pair p owns chunk g4*4+p (buffer p), 32x32 tiles =====
            for (int g4 = 0; g4 < 4; ++g4) {
                const int c = g4 * 4 + p;
                const int g = step * 32 + 16 + c;
                mb_wait(BARS + 8u * p, (uint32_t)(g4 & 1));

                float acc2[8][4];
                #pragma unroll
                for (int t = 0; t < 8; ++t)
                    #pragma unroll
                    for (int j = 0; j < 4; ++j) acc2[t][j] = 0.f;

                const uint32_t Bb = RING + (uint32_t)p * 32768u;
                #pragma unroll
                for (int kt = 0; kt < 4; ++kt) {
                    const uint32_t At = H2 + (uint32_t)kt * 4096u;
                    const uint32_t Bt = Bb + (uint32_t)kt * 8192u;
                    #pragma unroll
                    for (int ks = 0; ks < 4; ++ks) {
                        uint32_t a0[4], a1[4];
                        ldsm4(a0, At + swz(arow0 + ks * 32));
                        ldsm4(a1, At + swz(arow1 + ks * 32));
                        #pragma unroll
                        for (int h = 0; h < 2; ++h) {
                            uint32_t bb[4];
                            ldsm4(bb, Bt + swz(brow + (uint32_t)((pw * 32 + h * 16) * 128) + ks * 32));
                            mma16816(acc2[h * 2],     a0, bb);
                            mma16816(acc2[h * 2 + 1], a0, bb + 2);
                            mma16816(acc2[4 + h * 2],     a1, bb);
                            mma16816(acc2[4 + h * 2 + 1], a1, bb + 2);
                        }
                    }
                }
                nbar_sync(10 + p, 64);                    // pair consumed buffer p
                if (pw == 0 && lid == 0 && g + 4 < 96) {
                    mb_expect(BARS + 8u * p, 32768u);
                    bulkcp(Bb, chunk_src(g + 4), 32768u, BARS + 8u * p);
                }
                nbar_sync(7, 512);                        // consumed: SG free (E done prev group)
                // stage Gamma chunk (bf16) into SG cols p*64 + pw*32 ..
                #pragma unroll
                for (int t = 0; t < 8; ++t) {
                    const int mr = t >> 2, h = (t >> 1) & 1, n8 = t & 1;
                    const uint32_t co = (uint32_t)((p * 64 + pw * 32 + h * 16 + n8 * 8 + hc2) * 2);
                    sts32(SGu + (uint32_t)((mr * 16 + hr) * 520) + co,
                          bf2u(__float22bfloat162_rn(make_float2(acc2[t][0], acc2[t][1]))));
                    sts32(SGu + (uint32_t)((mr * 16 + hr + 8) * 520) + co,
                          bf2u(__float22bfloat162_rn(make_float2(acc2[t][2], acc2[t][3]))));
                }
                nbar_arrive(6, 512);                      // produced
            }
        } else {
            // ===== E warps: elementwise for 4 groups of 256 cols =====
            const float dcoef = dctab[step];
            const float* vsrc = (step == 0) ? v : g_vf;
            for (int g4 = 0; g4 < 4; ++g4) {
                nbar_sync(6, 512);                        // produced: SG group ready
                #pragma unroll
                for (int i = 0; i < 8; ++i) {
                    const int col = ec * 4 + i * 32;
                    const int d = g4 * 256 + col;
                    uint32_t w2[2];
                    lds64(w2, SGu + (uint32_t)(er * 520 + col * 2));
                    float2 ga = __bfloat1622float2(*(__nv_bfloat162*)&w2[0]);
                    float2 gb = __bfloat1622float2(*(__nv_bfloat162*)&w2[1]);
                    float4 f4 = *(const float4*)(force + egrow + d);
                    float4 v4 = *(const float4*)(vsrc + egrow + d);
                    float4 vn;
                    vn.x = v4.x + dcoef * (f4.x - ga.x);
                    vn.y = v4.y + dcoef * (f4.y - ga.y);
                    vn.z = v4.z + dcoef * (f4.z - gb.x);
                    vn.w = v4.w + dcoef * (f4.w - gb.y);
                    *(float4*)(g_vf + egrow + d) = vn;
                    const int cc = d >> 6, dl = d & 63;
                    sts64(SV + (uint32_t)cc * 4096u + swz((uint32_t)(er * 128 + dl * 2)),
                          bf2u(__float22bfloat162_rn(make_float2(vn.x, vn.y))),
                          bf2u(__float22bfloat162_rn(make_float2(vn.z, vn.w))));
                    float4* ox = (float4*)(out + egrow + d);
                    if (step == 0) {
                        float4 t;
                        t.x = K_C1f * v4.x + K_C2f * vn.x; t.y = K_C1f * v4.y + K_C2f * vn.y;
                        t.z = K_C1f * v4.z + K_C2f * vn.z; t.w = K_C1f * v4.w + K_C2f * vn.w;
                        *ox = t;
                    } else if (step == 1) {
                        float4 t = *ox;
                        t.x += K_C2f * vn.x; t.y += K_C2f * vn.y;
                        t.z += K_C2f * vn.z; t.w += K_C2f * vn.w;
                        *ox = t;
                    } else {
                        float4 t = *ox;
                        float4 x4 = *(const float4*)(x + egrow + d);
                        t.x = x4.x + K_DT * (t.x + K_C1f * vn.x);
                        t.y = x4.y + K_DT * (t.y + K_C1f * vn.y);
                        t.z = x4.z + K_DT * (t.z + K_C1f * vn.z);
                        t.w = x4.w + K_DT * (t.w + K_C1f * vn.w);
                        *ox = t;
                        *(float4*)(out + (size_t)BB * DD + egrow + d) = vn;
                    }
                }
                nbar_arrive(7, 512);                      // consumed
            }
            nbar_arrive(8, 512);                          // sv_ready: all SV tiles of this step written
        }
    }
}

extern "C" void kernel_launch(void* const* d_in, const int* in_sizes, int n_in,
                              void* d_out, int out_size)
{
    const float* x     = (const float*)d_in[0];
    const float* v     = (const float*)d_in[1];
    const float* force = (const float*)d_in[2];
    const float* U     = (const float*)d_in[3];
    const float* W     = (const float*)d_in[4];
    float* out = (float*)d_out;

    const int smem_bytes = 231488;
    cudaFuncSetAttribute(yoshida_mma8_kernel, cudaFuncAttributeMaxDynamicSharedMemorySize, smem_bytes);

    prep_uw_kernel<<<1024, 256>>>(U, W);
    yoshida_mma8_kernel<<<NCTA, NTHR, smem_bytes>>>(x, v, force, out);
}

// round 15
// speedup vs baseline: 1.1023x; 1.1023x over previous
#include <cuda_runtime.h>
#include <cuda_bf16.h>
#include <stdint.h>

#define BB 4096
#define DD 1024
#define RR 256
#define NCTA 128
#define NTHR 512

#define K_W1 1.3512071919596578
#define K_W0 (-1.7024143839193153)
#define K_C1f ((float)(K_W1 * 0.5))
#define K_C2f ((float)((K_W0 + K_W1) * 0.5))
#define K_DT 0.01f

// -------- device-global scratch (no runtime allocation) --------
__device__ __align__(1024) unsigned char g_Ub[16 * 32768];   // U bf16: 16 k-chunks [256n x 64k] SW128
__device__ __align__(1024) unsigned char g_Wb[64 * 8192];    // W bf16: 16 n-chunks x 4 k-tiles [64n x 64k] SW128
__device__ __align__(1024) float g_vf[(size_t)BB * DD];      // v fp32 master

// -------- helpers --------
__device__ __forceinline__ uint32_t swz(uint32_t o) { return o ^ ((o >> 3) & 0x70); }
__device__ __forceinline__ uint32_t s2u(const void* p) {
    uint32_t a; asm("{ .reg .u64 t; cvta.to.shared.u64 t, %1; cvt.u32.u64 %0, t; }" : "=r"(a) : "l"(p)); return a;
}
__device__ __forceinline__ uint32_t bf2u(__nv_bfloat162 b) { return *reinterpret_cast<uint32_t*>(&b); }
__device__ __forceinline__ void mb_init(uint32_t a, uint32_t c) {
    asm volatile("mbarrier.init.shared.b64 [%0], %1;" :: "r"(a), "r"(c) : "memory");
}
__device__ __forceinline__ void mb_expect(uint32_t a, uint32_t b) {
    asm volatile("mbarrier.arrive.expect_tx.shared.b64 _, [%0], %1;" :: "r"(a), "r"(b) : "memory");
}
__device__ __forceinline__ void mb_wait(uint32_t a, uint32_t p) {
    asm volatile("{\n\t.reg .pred P;\n\tLW%=:\n\t"
        "mbarrier.try_wait.parity.acquire.cta.shared::cta.b64 P, [%0], %1, 0x989680;\n\t"
        "@P bra LD%=;\n\tbra LW%=;\n\tLD%=:\n\t}" :: "r"(a), "r"(p) : "memory");
}
__device__ __forceinline__ void bulkcp(uint32_t d, const void* s, uint32_t n, uint32_t mb) {
    asm volatile("cp.async.bulk.shared::cluster.global.mbarrier::complete_tx::bytes [%0], [%1], %2, [%3];"
                 :: "r"(d), "l"(s), "r"(n), "r"(mb) : "memory");
}
__device__ __forceinline__ void fence_async_sh() { asm volatile("fence.proxy.async.shared::cta;" ::: "memory"); }
__device__ __forceinline__ void nbar_sync(int id, int cnt) {
    asm volatile("bar.sync %0, %1;" :: "r"(id), "r"(cnt) : "memory");
}
__device__ __forceinline__ void nbar_arrive(int id, int cnt) {
    asm volatile("bar.arrive %0, %1;" :: "r"(id), "r"(cnt) : "memory");
}
__device__ __forceinline__ void ldsm4(uint32_t* r, uint32_t a) {
    asm volatile("ldmatrix.sync.aligned.m8n8.x4.shared.b16 {%0,%1,%2,%3}, [%4];"
                 : "=r"(r[0]), "=r"(r[1]), "=r"(r[2]), "=r"(r[3]) : "r"(a));
}
__device__ __forceinline__ void lds128(uint32_t* r, uint32_t a) {
    asm volatile("ld.shared.v4.u32 {%0,%1,%2,%3}, [%4];"
                 : "=r"(r[0]), "=r"(r[1]), "=r"(r[2]), "=r"(r[3]) : "r"(a));
}
__device__ __forceinline__ void sts128(uint32_t a, const uint32_t* r) {
    asm volatile("st.shared.v4.b32 [%0], {%1,%2,%3,%4};"
                 :: "r"(a), "r"(r[0]), "r"(r[1]), "r"(r[2]), "r"(r[3]) : "memory");
}
__device__ __forceinline__ void mma16816(float* c, const uint32_t* a, const uint32_t* b) {
    asm volatile("mma.sync.aligned.m16n8k16.row.col.f32.bf16.bf16.f32 "
        "{%0,%1,%2,%3}, {%4,%5,%6,%7}, {%8,%9}, {%0,%1,%2,%3};"
        : "+f"(c[0]), "+f"(c[1]), "+f"(c[2]), "+f"(c[3])
        : "r"(a[0]), "r"(a[1]), "r"(a[2]), "r"(a[3]), "r"(b[0]), "r"(b[1]));
}
__device__ __forceinline__ void sts32(uint32_t a, uint32_t v) {
    asm volatile("st.shared.b32 [%0], %1;" :: "r"(a), "r"(v) : "memory");
}
__device__ __forceinline__ void sts64(uint32_t a, uint32_t v0, uint32_t v1) {
    asm volatile("st.shared.v2.u32 [%0], {%1, %2};" :: "r"(a), "r"(v0), "r"(v1) : "memory");
}
__device__ __forceinline__ const unsigned char* chunk_src(int g) {
    int l = g & 31;
    return (l < 16) ? (g_Ub + (size_t)l * 32768) : (g_Wb + (size_t)(l - 16) * 32768);
}
// Issue the load for global chunk gc into its buffer, signaling the right barrier:
// GEMM1 chunks (local 0..15) -> ring barrier (l&3); GEMM2 chunks (16..31) -> chunk barrier l-16.
__device__ __forceinline__ void issue_chunk(int gc, uint32_t RING, uint32_t BARS) {
    const int l = gc & 31;
    const uint32_t bar = (l < 16) ? (BARS + 8u * (uint32_t)(l & 3))
                                  : (BARS + 32u + 8u * (uint32_t)(l - 16));
    mb_expect(bar, 32768u);
    bulkcp(RING + 32768u * (uint32_t)(l & 3), chunk_src(gc), 32768u, bar);
}

// -------- prologue: fp32 -> bf16 SW128 tiles in gmem --------
__global__ void prep_uw_kernel(const float* __restrict__ U, const float* __restrict__ W) {
    int idx = blockIdx.x * blockDim.x + threadIdx.x;       // 262144
    if (idx < 131072) {
        int kc = idx >> 13, rem = idx & 8191, r = rem >> 5, j = rem & 31;
        float2 f = *(const float2*)(U + (size_t)r * DD + kc * 64 + j * 2);
        *(uint32_t*)(g_Ub + kc * 32768 + swz((uint32_t)(r * 128 + j * 4))) = bf2u(__float22bfloat162_rn(f));
    } else {
        int i2 = idx - 131072;
        int t = i2 >> 11, rem = i2 & 2047, dr = rem >> 5, j = rem & 31;
        int nc = t >> 2, kt = t & 3;
        float2 f = *(const float2*)(W + (size_t)(nc * 64 + dr) * RR + kt * 64 + j * 2);
        *(uint32_t*)(g_Wb + t * 8192 + swz((uint32_t)(dr * 128 + j * 4))) = bf2u(__float22bfloat162_rn(f));
    }
}

// -------- main fused integrator --------
__global__ __launch_bounds__(NTHR, 1)
void yoshida_mma11_kernel(const float* __restrict__ x, const float* __restrict__ v,
                          const float* __restrict__ force, float* __restrict__ out) {
    extern __shared__ unsigned char dsm[];
    unsigned char* basep = (unsigned char*)(((uintptr_t)dsm + 1023u) & ~(uintptr_t)1023u);
    const uint32_t base = s2u(basep);
    const uint32_t SV   = base;                 // 64KB v bf16 / Gamma staging: 16 tiles [32 x 64] SW128
    const uint32_t RING = base + 65536u;        // 4 x 32KB unified U/W chunk ring
    const uint32_t H2   = base + 196608u;       // 4 x 4KB h^2 tiles [32 x 64] bf16 SW128
    const uint32_t BARS = base + 212992u;       // ring mbars[4] @ +0, chunk mbars[16] @ +32

    const int tid = threadIdx.x, wid = tid >> 5, lid = tid & 31;
    const int mh = wid >> 3;                   // GEMM1 M half
    const int q  = wid & 7;                    // GEMM1 N octant
    const int row0 = blockIdx.x * 32;

    const uint32_t arow  = (uint32_t)((mh * 16 + (lid & 15)) * 128 + ((lid >> 4) << 4)); // GEMM1 A
    const uint32_t arow0 = (uint32_t)((lid & 15) * 128 + ((lid >> 4) << 4));             // GEMM2 A rows 0-15
    const uint32_t arow1 = arow0 + 2048u;                                                // GEMM2 A rows 16-31
    const uint32_t brow  = (uint32_t)(((lid & 7) + ((lid >> 4) << 3)) * 128 + (((lid >> 3) & 1) << 4));
    const int hr = lid >> 2, hc2 = (lid & 3) * 2;
    // E-warp ew mapping (warps 8-15)
    const int et = tid & 255;
    const int er = et >> 3, ec = et & 7;
    const size_t egrow = (size_t)(row0 + er) * DD;

    if (tid == 0) {
        #pragma unroll
        for (int i = 0; i < 4; ++i) mb_init(BARS + 8u * i, 1);
        #pragma unroll
        for (int i = 0; i < 16; ++i) mb_init(BARS + 32u + 8u * i, 1);
        fence_async_sh();
        #pragma unroll
        for (int c = 0; c < 4; ++c) issue_chunk(c, RING, BARS);   // prime GEMM1 chunks 0-3
    }

    // resident sV init: bf16(v) pre-swizzled
    for (int i = tid; i < 8192; i += NTHR) {
        int row = i >> 8, rem = i & 255, kc = rem >> 4, jj = rem & 15;
        float4 f = *(const float4*)(v + (size_t)(row0 + row) * DD + kc * 64 + jj * 4);
        sts64(SV + (uint32_t)kc * 4096u + swz((uint32_t)(row * 128 + jj * 8)),
              bf2u(__float22bfloat162_rn(make_float2(f.x, f.y))),
              bf2u(__float22bfloat162_rn(make_float2(f.z, f.w))));
    }
    __syncthreads();

    const float dctab[3] = { (float)K_W1 * K_DT, (float)K_W0 * K_DT, (float)K_W1 * K_DT };

    for (int step = 0; step < 3; ++step) {
        // ===== GEMM1: h[32 x 256] = sV @ U^T, 8 chunk-pairs, all 16 warps =====
        float acc1[4][4];
        #pragma unroll
        for (int t = 0; t < 4; ++t)
            #pragma unroll
            for (int j = 0; j < 4; ++j) acc1[t][j] = 0.f;

        for (int kp = 0; kp < 8; ++kp) {
            const int g = step * 32 + kp * 2;
            const int b0 = (kp * 2) & 3;
            const uint32_t ph = (uint32_t)((g >> 2) & 1);   // = (kc>>2)&1; 4 ring loads/step
            mb_wait(BARS + 8u * b0, ph);
            mb_wait(BARS + 8u * (b0 + 1), ph);
            #pragma unroll
            for (int cc = 0; cc < 2; ++cc) {
                const uint32_t Ab = SV + (uint32_t)(kp * 2 + cc) * 4096u;
                const uint32_t Bb = RING + (uint32_t)(b0 + cc) * 32768u;
                #pragma unroll
                for (int ks = 0; ks < 4; ++ks) {
                    uint32_t a[4];
                    ldsm4(a, Ab + swz(arow + ks * 32));
                    #pragma unroll
                    for (int ntp = 0; ntp < 2; ++ntp) {
                        uint32_t bb[4];
                        ldsm4(bb, Bb + swz(brow + (uint32_t)((q * 32 + ntp * 16) * 128) + ks * 32));
                        mma16816(acc1[2 * ntp],     a, bb);
                        mma16816(acc1[2 * ntp + 1], a, bb + 2);
                    }
                }
            }
            __syncthreads();
            if (tid == 0) {
                issue_chunk(g + 4, RING, BARS);   // local 4..19: ring or chunk barrier
                issue_chunk(g + 5, RING, BARS);
            }
        }

        // ---- h^2 -> bf16 SW128 H2 tiles ----
        {
            const uint32_t ht = H2 + (uint32_t)(q >> 1) * 4096u;
            #pragma unroll
            for (int t = 0; t < 4; ++t) {
                const int ntp = t >> 1, half = t & 1;
                float c0 = acc1[t][0], c1 = acc1[t][1], c2 = acc1[t][2], c3 = acc1[t][3];
                uint32_t p0 = bf2u(__float22bfloat162_rn(make_float2(c0 * c0, c1 * c1)));
                uint32_t p1 = bf2u(__float22bfloat162_rn(make_float2(c2 * c2, c3 * c3)));
                uint32_t koff = (uint32_t)(((q & 1) * 32 + ntp * 16 + half * 8 + hc2) * 2);
                sts32(ht + swz((uint32_t)((mh * 16 + hr) * 128) + koff), p0);
                sts32(ht + swz((uint32_t)((mh * 16 + hr + 8) * 128) + koff), p1);
            }
        }
        __syncthreads();    // H2 complete; SV v-values fully consumed

        // ===== GEMM2: 8 G warps (whole 32Mx64N chunks, Gamma -> SV in place) + 8 E warps =====
        if (wid < 8) {
            #pragma unroll
            for (int half = 0; half < 2; ++half) {
                const int ci = wid + half * 8;                 // local GEMM2 chunk 0..15
                const int gc = step * 32 + 16 + ci;
                // single-waiter chunk barrier: one phase per step -> parity = step&1
                mb_wait(BARS + 32u + 8u * (uint32_t)ci, (uint32_t)(step & 1));

                float acc[16][4];
                #pragma unroll
                for (int t = 0; t < 16; ++t)
                    #pragma unroll
                    for (int j = 0; j < 4; ++j) acc[t][j] = 0.f;

                const uint32_t Bb = RING + (uint32_t)(ci & 3) * 32768u;
                #pragma unroll
                for (int kt = 0; kt < 4; ++kt) {
                    const uint32_t At = H2 + (uint32_t)kt * 4096u;
                    const uint32_t Bt = Bb + (uint32_t)kt * 8192u;
                    #pragma unroll
                    for (int ks = 0; ks < 4; ++ks) {
                        uint32_t a0[4], a1[4];
                        ldsm4(a0, At + swz(arow0 + ks * 32));
                        ldsm4(a1, At + swz(arow1 + ks * 32));
                        #pragma unroll
                        for (int nt = 0; nt < 4; ++nt) {
                            uint32_t bb[4];
                            ldsm4(bb, Bt + swz(brow + (uint32_t)((nt * 16) * 128) + ks * 32));
                            mma16816(acc[nt * 2],         a0, bb);
                            mma16816(acc[nt * 2 + 1],     a0, bb + 2);
                            mma16816(acc[8 + nt * 2],     a1, bb);
                            mma16816(acc[8 + nt * 2 + 1], a1, bb + 2);
                        }
                    }
                }
                // this warp was the sole consumer of buffer (ci&3)'s current occupant:
                // issue the buffer's next occupant (chunk gc+4; next step's GEMM1 when ci>=12)
                if (lid == 0 && gc + 4 < 96) issue_chunk(gc + 4, RING, BARS);

                // stage Gamma chunk ci -> SV tile ci (bf16, SW128); v there is dead
                {
                    const uint32_t dst = SV + (uint32_t)ci * 4096u;
                    #pragma unroll
                    for (int t = 0; t < 16; ++t) {
                        const int mr = t >> 3, nt = (t >> 1) & 3, nh = t & 1;
                        const uint32_t co = (uint32_t)((nt * 16 + nh * 8 + hc2) * 2);
                        sts32(dst + swz((uint32_t)((mr * 16 + hr) * 128) + co),
                              bf2u(__float22bfloat162_rn(make_float2(acc[t][0], acc[t][1]))));
                        sts32(dst + swz((uint32_t)((mr * 16 + hr + 8) * 128) + co),
                              bf2u(__float22bfloat162_rn(make_float2(acc[t][2], acc[t][3]))));
                    }
                }
                nbar_arrive(2 + (ci >> 2), 384);          // produce round ci>>2
            }
        } else {
            const float dcoef = dctab[step];
            const float* vsrc = (step == 0) ? v : g_vf;
            for (int r = 0; r < 4; ++r) {
                nbar_sync(2 + r, 384);                    // Gamma tiles 4r..4r+3 staged
                #pragma unroll
                for (int cc = 0; cc < 4; ++cc) {
                    const int c = r * 4 + cc;
                    const uint32_t gaddr = SV + (uint32_t)c * 4096u + swz((uint32_t)(er * 128 + ec * 16));
                    uint32_t wv[4];
                    lds128(wv, gaddr);
                    float2 g0 = __bfloat1622float2(*(__nv_bfloat162*)&wv[0]);
                    float2 g1 = __bfloat1622float2(*(__nv_bfloat162*)&wv[1]);
                    float2 g2 = __bfloat1622float2(*(__nv_bfloat162*)&wv[2]);
                    float2 g3 = __bfloat1622float2(*(__nv_bfloat162*)&wv[3]);
                    const int d = c * 64 + ec * 8;
                    float4 fa = *(const float4*)(force + egrow + d);
                    float4 fb = *(const float4*)(force + egrow + d + 4);
                    float4 va = *(const float4*)(vsrc + egrow + d);
                    float4 vb = *(const float4*)(vsrc + egrow + d + 4);
                    float4 na, nb;
                    na.x = va.x + dcoef * (fa.x - g0.x);
                    na.y = va.y + dcoef * (fa.y - g0.y);
                    na.z = va.z + dcoef * (fa.z - g1.x);
                    na.w = va.w + dcoef * (fa.w - g1.y);
                    nb.x = vb.x + dcoef * (fb.x - g2.x);
                    nb.y = vb.y + dcoef * (fb.y - g2.y);
                    nb.z = vb.z + dcoef * (fb.z - g3.x);
                    nb.w = vb.w + dcoef * (fb.w - g3.y);
                    *(float4*)(g_vf + egrow + d)     = na;
                    *(float4*)(g_vf + egrow + d + 4) = nb;
                    wv[0] = bf2u(__float22bfloat162_rn(make_float2(na.x, na.y)));
                    wv[1] = bf2u(__float22bfloat162_rn(make_float2(na.z, na.w)));
                    wv[2] = bf2u(__float22bfloat162_rn(make_float2(nb.x, nb.y)));
                    wv[3] = bf2u(__float22bfloat162_rn(make_float2(nb.z, nb.w)));
                    sts128(gaddr, wv);                    // vn bf16 back into SV tile c
                    float4* oxa = (float4*)(out + egrow + d);
                    float4* oxb = (float4*)(out + egrow + d + 4);
                    if (step == 0) {
                        float4 ta, tb;
                        ta.x = K_C1f * va.x + K_C2f * na.x; ta.y = K_C1f * va.y + K_C2f * na.y;
                        ta.z = K_C1f * va.z + K_C2f * na.z; ta.w = K_C1f * va.w + K_C2f * na.w;
                        tb.x = K_C1f * vb.x + K_C2f * nb.x; tb.y = K_C1f * vb.y + K_C2f * nb.y;
                        tb.z = K_C1f * vb.z + K_C2f * nb.z; tb.w = K_C1f * vb.w + K_C2f * nb.w;
                        *oxa = ta; *oxb = tb;
                    } else if (step == 1) {
                        float4 ta = *oxa, tb = *oxb;
                        ta.x += K_C2f * na.x; ta.y += K_C2f * na.y;
                        ta.z += K_C2f * na.z; ta.w += K_C2f * na.w;
                        tb.x += K_C2f * nb.x; tb.y += K_C2f * nb.y;
                        tb.z += K_C2f * nb.z; tb.w += K_C2f * nb.w;
                        *oxa = ta; *oxb = tb;
                    } else {
                        float4 ta = *oxa, tb = *oxb;
                        float4 xa = *(const float4*)(x + egrow + d);
                        float4 xb = *(const float4*)(x + egrow + d + 4);
                        ta.x = xa.x + K_DT * (ta.x + K_C1f * na.x);
                        ta.y = xa.y + K_DT * (ta.y + K_C1f * na.y);
                        ta.z = xa.z + K_DT * (ta.z + K_C1f * na.z);
                        ta.w = xa.w + K_DT * (ta.w + K_C1f * na.w);
                        tb.x = xb.x + K_DT * (tb.x + K_C1f * nb.x);
                        tb.y = xb.y + K_DT * (tb.y + K_C1f * nb.y);
                        tb.z = xb.z + K_DT * (tb.z + K_C1f * nb.z);
                        tb.w = xb.w + K_DT * (tb.w + K_C1f * nb.w);
                        *oxa = ta; *oxb = tb;
                        *(float4*)(out + (size_t)BB * DD + egrow + d)     = na;
                        *(float4*)(out + (size_t)BB * DD + egrow + d + 4) = nb;
                    }
                }
            }
        }
        __syncthreads();    // SV fully holds vn before next step's GEMM1
    }
}

extern "C" void kernel_launch(void* const* d_in, const int* in_sizes, int n_in,
                              void* d_out, int out_size)
{
    const float* x     = (const float*)d_in[0];
    const float* v     = (const float*)d_in[1];
    const float* force = (const float*)d_in[2];
    const float* U     = (const float*)d_in[3];
    const float* W     = (const float*)d_in[4];
    float* out = (float*)d_out;

    const int smem_bytes = 214144;
    cudaFuncSetAttribute(yoshida_mma11_kernel, cudaFuncAttributeMaxDynamicSharedMemorySize, smem_bytes);

    prep_uw_kernel<<<1024, 256>>>(U, W);
    yoshida_mma11_kernel<<<NCTA, NTHR, smem_bytes>>>(x, v, force, out);
}

// round 16
// speedup vs baseline: 1.2349x; 1.1203x over previous
#include <cuda_runtime.h>
#include <cuda_bf16.h>
#include <stdint.h>

#define BB 4096
#define DD 1024
#define RR 256
#define NCTA 128
#define NTHR 512

#define K_W1 1.3512071919596578
#define K_W0 (-1.7024143839193153)
#define K_C1f ((float)(K_W1 * 0.5))
#define K_C2f ((float)((K_W0 + K_W1) * 0.5))
#define K_DT 0.01f

__device__ __align__(1024) unsigned char g_Ub[16 * 32768];   // U bf16: 16 k-chunks [256n x 64k] SW128
__device__ __align__(1024) unsigned char g_Wb[64 * 8192];    // W bf16: 16 n-chunks x 4 k-tiles [64n x 64k] SW128
__device__ __align__(1024) float g_vf[(size_t)BB * DD];      // v fp32 master

__device__ __forceinline__ uint32_t swz(uint32_t o) { return o ^ ((o >> 3) & 0x70); }
__device__ __forceinline__ uint32_t s2u(const void* p) {
    uint32_t a; asm("{ .reg .u64 t; cvta.to.shared.u64 t, %1; cvt.u32.u64 %0, t; }" : "=r"(a) : "l"(p)); return a;
}
__device__ __forceinline__ uint32_t bf2u(__nv_bfloat162 b) { return *reinterpret_cast<uint32_t*>(&b); }
__device__ __forceinline__ void mb_init(uint32_t a, uint32_t c) {
    asm volatile("mbarrier.init.shared.b64 [%0], %1;" :: "r"(a), "r"(c) : "memory");
}
__device__ __forceinline__ void mb_expect(uint32_t a, uint32_t b) {
    asm volatile("mbarrier.arrive.expect_tx.shared.b64 _, [%0], %1;" :: "r"(a), "r"(b) : "memory");
}
__device__ __forceinline__ void mb_wait(uint32_t a, uint32_t p) {
    asm volatile("{\n\t.reg .pred P;\n\tLW%=:\n\t"
        "mbarrier.try_wait.parity.acquire.cta.shared::cta.b64 P, [%0], %1, 0x989680;\n\t"
        "@P bra LD%=;\n\tbra LW%=;\n\tLD%=:\n\t}" :: "r"(a), "r"(p) : "memory");
}
__device__ __forceinline__ void bulkcp(uint32_t d, const void* s, uint32_t n, uint32_t mb) {
    asm volatile("cp.async.bulk.shared::cluster.global.mbarrier::complete_tx::bytes [%0], [%1], %2, [%3];"
                 :: "r"(d), "l"(s), "r"(n), "r"(mb) : "memory");
}
__device__ __forceinline__ void fence_async_sh() { asm volatile("fence.proxy.async.shared::cta;" ::: "memory"); }
__device__ __forceinline__ void nbar_sync(int id, int cnt) {
    asm volatile("bar.sync %0, %1;" :: "r"(id), "r"(cnt) : "memory");
}
__device__ __forceinline__ void nbar_arrive(int id, int cnt) {
    asm volatile("bar.arrive %0, %1;" :: "r"(id), "r"(cnt) : "memory");
}
__device__ __forceinline__ void ldsm4(uint32_t* r, uint32_t a) {
    asm volatile("ldmatrix.sync.aligned.m8n8.x4.shared.b16 {%0,%1,%2,%3}, [%4];"
                 : "=r"(r[0]), "=r"(r[1]), "=r"(r[2]), "=r"(r[3]) : "r"(a));
}
__device__ __forceinline__ void lds128(uint32_t* r, uint32_t a) {
    asm volatile("ld.shared.v4.u32 {%0,%1,%2,%3}, [%4];"
                 : "=r"(r[0]), "=r"(r[1]), "=r"(r[2]), "=r"(r[3]) : "r"(a));
}
__device__ __forceinline__ void sts128(uint32_t a, const uint32_t* r) {
    asm volatile("st.shared.v4.b32 [%0], {%1,%2,%3,%4};"
                 :: "r"(a), "r"(r[0]), "r"(r[1]), "r"(r[2]), "r"(r[3]) : "memory");
}
__device__ __forceinline__ void mma16816(float* c, const uint32_t* a, const uint32_t* b) {
    asm volatile("mma.sync.aligned.m16n8k16.row.col.f32.bf16.bf16.f32 "
        "{%0,%1,%2,%3}, {%4,%5,%6,%7}, {%8,%9}, {%0,%1,%2,%3};"
        : "+f"(c[0]), "+f"(c[1]), "+f"(c[2]), "+f"(c[3])
        : "r"(a[0]), "r"(a[1]), "r"(a[2]), "r"(a[3]), "r"(b[0]), "r"(b[1]));
}
__device__ __forceinline__ void sts32(uint32_t a, uint32_t v) {
    asm volatile("st.shared.b32 [%0], %1;" :: "r"(a), "r"(v) : "memory");
}
__device__ __forceinline__ void sts64(uint32_t a, uint32_t v0, uint32_t v1) {
    asm volatile("st.shared.v2.u32 [%0], {%1, %2};" :: "r"(a), "r"(v0), "r"(v1) : "memory");
}
__device__ __forceinline__ const unsigned char* chunk_src(int g) {
    int l = g & 31;
    return (l < 16) ? (g_Ub + (size_t)l * 32768) : (g_Wb + (size_t)(l - 16) * 32768);
}
__device__ __forceinline__ void issue_chunk(int gc, uint32_t RING, uint32_t BARS) {
    const int l = gc & 31;
    const uint32_t bar = (l < 16) ? (BARS + 8u * (uint32_t)(l & 3))
                                  : (BARS + 32u + 8u * (uint32_t)(l - 16));
    mb_expect(bar, 32768u);
    bulkcp(RING + 32768u * (uint32_t)(l & 3), chunk_src(gc), 32768u, bar);
}

__global__ void prep_uw_kernel(const float* __restrict__ U, const float* __restrict__ W) {
    int idx = blockIdx.x * blockDim.x + threadIdx.x;
    if (idx < 131072) {
        int kc = idx >> 13, rem = idx & 8191, r = rem >> 5, j = rem & 31;
        float2 f = *(const float2*)(U + (size_t)r * DD + kc * 64 + j * 2);
        *(uint32_t*)(g_Ub + kc * 32768 + swz((uint32_t)(r * 128 + j * 4))) = bf2u(__float22bfloat162_rn(f));
    } else {
        int i2 = idx - 131072;
        int t = i2 >> 11, rem = i2 & 2047, dr = rem >> 5, j = rem & 31;
        int nc = t >> 2, kt = t & 3;
        float2 f = *(const float2*)(W + (size_t)(nc * 64 + dr) * RR + kt * 64 + j * 2);
        *(uint32_t*)(g_Wb + t * 8192 + swz((uint32_t)(dr * 128 + j * 4))) = bf2u(__float22bfloat162_rn(f));
    }
}

__global__ __launch_bounds__(NTHR, 1)
void yoshida_mma12_kernel(const float* __restrict__ x, const float* __restrict__ v,
                          const float* __restrict__ force, float* __restrict__ out) {
    extern __shared__ unsigned char dsm[];
    unsigned char* basep = (unsigned char*)(((uintptr_t)dsm + 1023u) & ~(uintptr_t)1023u);
    const uint32_t base = s2u(basep);
    const uint32_t SV   = base;                 // 64KB v bf16 / Gamma staging: 16 tiles [32 x 64] SW128
    const uint32_t RING = base + 65536u;        // 4 x 32KB unified U/W chunk ring
    const uint32_t H2   = base + 196608u;       // 4 x 4KB h^2 tiles
    const uint32_t BARS = base + 212992u;       // ring mbars[4] @ +0, chunk mbars[16] @ +32

    const int tid = threadIdx.x, wid = tid >> 5, lid = tid & 31;
    const int row0 = blockIdx.x * 32;
    const int q = wid & 7;

    const uint32_t arow0 = (uint32_t)((lid & 15) * 128 + ((lid >> 4) << 4));   // rows 0-15
    const uint32_t arow1 = arow0 + 2048u;                                      // rows 16-31
    const uint32_t brow  = (uint32_t)(((lid & 7) + ((lid >> 4) << 3)) * 128 + (((lid >> 3) & 1) << 4));
    const int hr = lid >> 2, hc2 = (lid & 3) * 2;
    const int et = tid & 255;
    const int er = et >> 3, ec = et & 7;
    const size_t egrow = (size_t)(row0 + er) * DD;

    if (tid == 0) {
        #pragma unroll
        for (int i = 0; i < 4; ++i) mb_init(BARS + 8u * i, 1);
        #pragma unroll
        for (int i = 0; i < 16; ++i) mb_init(BARS + 32u + 8u * i, 1);
        fence_async_sh();
        #pragma unroll
        for (int c = 0; c < 4; ++c) issue_chunk(c, RING, BARS);
    }

    for (int i = tid; i < 8192; i += NTHR) {
        int row = i >> 8, rem = i & 255, kc = rem >> 4, jj = rem & 15;
        float4 f = *(const float4*)(v + (size_t)(row0 + row) * DD + kc * 64 + jj * 4);
        sts64(SV + (uint32_t)kc * 4096u + swz((uint32_t)(row * 128 + jj * 8)),
              bf2u(__float22bfloat162_rn(make_float2(f.x, f.y))),
              bf2u(__float22bfloat162_rn(make_float2(f.z, f.w))));
    }
    __syncthreads();

    const float dctab[3] = { (float)K_W1 * K_DT, (float)K_W0 * K_DT, (float)K_W1 * K_DT };

    for (int step = 0; step < 3; ++step) {
        if (wid < 8) {
            // ===== GEMM1 on 8 G warps: 32M x 32N tiles, 8 chunk-pairs =====
            float acc1[8][4];
            #pragma unroll
            for (int t = 0; t < 8; ++t)
                #pragma unroll
                for (int j = 0; j < 4; ++j) acc1[t][j] = 0.f;

            for (int kp = 0; kp < 8; ++kp) {
                if (step > 0 && (kp & 1) == 0)
                    nbar_sync(6 + (kp >> 1), 512);        // E's ew(s-1) wrote SV tiles 4r..4r+3
                const int g = step * 32 + kp * 2;
                const int b0 = (kp * 2) & 3;
                const uint32_t ph = (uint32_t)((g >> 2) & 1);
                mb_wait(BARS + 8u * b0, ph);
                mb_wait(BARS + 8u * (b0 + 1), ph);
                #pragma unroll
                for (int cc = 0; cc < 2; ++cc) {
                    const uint32_t Ab = SV + (uint32_t)(kp * 2 + cc) * 4096u;
                    const uint32_t Bb = RING + (uint32_t)(b0 + cc) * 32768u;
                    #pragma unroll
                    for (int ks = 0; ks < 4; ++ks) {
                        uint32_t a0[4], a1[4];
                        ldsm4(a0, Ab + swz(arow0 + ks * 32));
                        ldsm4(a1, Ab + swz(arow1 + ks * 32));
                        #pragma unroll
                        for (int h = 0; h < 2; ++h) {
                            uint32_t bb[4];
                            ldsm4(bb, Bb + swz(brow + (uint32_t)((q * 32 + h * 16) * 128) + ks * 32));
                            mma16816(acc1[h * 2],     a0, bb);
                            mma16816(acc1[h * 2 + 1], a0, bb + 2);
                            mma16816(acc1[4 + h * 2],     a1, bb);
                            mma16816(acc1[4 + h * 2 + 1], a1, bb + 2);
                        }
                    }
                }
                nbar_sync(1, 256);                        // all G warps consumed the pair
                if (wid == 0 && lid == 0) {
                    issue_chunk(g + 4, RING, BARS);
                    issue_chunk(g + 5, RING, BARS);
                }
            }

            // ---- h^2 -> H2 bf16 tiles (warp q owns 32 cols, all 32 rows) ----
            {
                const uint32_t ht = H2 + (uint32_t)(q >> 1) * 4096u;
                #pragma unroll
                for (int t = 0; t < 8; ++t) {
                    const int mr = t >> 2, h = (t >> 1) & 1, n8 = t & 1;
                    const uint32_t koff = (uint32_t)(((q & 1) * 32 + h * 16 + n8 * 8 + hc2) * 2);
                    float c0 = acc1[t][0], c1 = acc1[t][1], c2 = acc1[t][2], c3 = acc1[t][3];
                    sts32(ht + swz((uint32_t)((mr * 16 + hr) * 128) + koff),
                          bf2u(__float22bfloat162_rn(make_float2(c0 * c0, c1 * c1))));
                    sts32(ht + swz((uint32_t)((mr * 16 + hr + 8) * 128) + koff),
                          bf2u(__float22bfloat162_rn(make_float2(c2 * c2, c3 * c3))));
                }
            }
            nbar_sync(1, 256);                            // H2 visible to all G warps

            // ===== GEMM2: warp owns whole 32Mx64N chunk; Gamma -> SV in place =====
            #pragma unroll
            for (int half = 0; half < 2; ++half) {
                const int ci = wid + half * 8;
                const int gc = step * 32 + 16 + ci;
                mb_wait(BARS + 32u + 8u * (uint32_t)ci, (uint32_t)(step & 1));

                float acc[16][4];
                #pragma unroll
                for (int t = 0; t < 16; ++t)
                    #pragma unroll
                    for (int j = 0; j < 4; ++j) acc[t][j] = 0.f;

                const uint32_t Bb = RING + (uint32_t)(ci & 3) * 32768u;
                #pragma unroll
                for (int kt = 0; kt < 4; ++kt) {
                    const uint32_t At = H2 + (uint32_t)kt * 4096u;
                    const uint32_t Bt = Bb + (uint32_t)kt * 8192u;
                    #pragma unroll
                    for (int ks = 0; ks < 4; ++ks) {
                        uint32_t a0[4], a1[4];
                        ldsm4(a0, At + swz(arow0 + ks * 32));
                        ldsm4(a1, At + swz(arow1 + ks * 32));
                        #pragma unroll
                        for (int nt = 0; nt < 4; ++nt) {
                            uint32_t bb[4];
                            ldsm4(bb, Bt + swz(brow + (uint32_t)((nt * 16) * 128) + ks * 32));
                            mma16816(acc[nt * 2],         a0, bb);
                            mma16816(acc[nt * 2 + 1],     a0, bb + 2);
                            mma16816(acc[8 + nt * 2],     a1, bb);
                            mma16816(acc[8 + nt * 2 + 1], a1, bb + 2);
                        }
                    }
                }
                if (lid == 0 && gc + 4 < 96) issue_chunk(gc + 4, RING, BARS);
                {
                    const uint32_t dst = SV + (uint32_t)ci * 4096u;
                    #pragma unroll
                    for (int t = 0; t < 16; ++t) {
                        const int mr = t >> 3, nt = (t >> 1) & 3, nh = t & 1;
                        const uint32_t co = (uint32_t)((nt * 16 + nh * 8 + hc2) * 2);
                        sts32(dst + swz((uint32_t)((mr * 16 + hr) * 128) + co),
                              bf2u(__float22bfloat162_rn(make_float2(acc[t][0], acc[t][1]))));
                        sts32(dst + swz((uint32_t)((mr * 16 + hr + 8) * 128) + co),
                              bf2u(__float22bfloat162_rn(make_float2(acc[t][2], acc[t][3]))));
                    }
                }
                nbar_arrive(2 + (ci >> 2), 384);
            }
        } else {
            // ===== E warps: ew(step), gated per round; arrivals enable GEMM1(step+1) =====
            const float dcoef = dctab[step];
            const float* vsrc = (step == 0) ? v : g_vf;
            for (int r = 0; r < 4; ++r) {
                nbar_sync(2 + r, 384);                    // Gamma tiles 4r..4r+3 staged
                #pragma unroll
                for (int cc = 0; cc < 4; ++cc) {
                    const int c = r * 4 + cc;
                    const uint32_t gaddr = SV + (uint32_t)c * 4096u + swz((uint32_t)(er * 128 + ec * 16));
                    uint32_t wv[4];
                    lds128(wv, gaddr);
                    float2 g0 = __bfloat1622float2(*(__nv_bfloat162*)&wv[0]);
                    float2 g1 = __bfloat1622float2(*(__nv_bfloat162*)&wv[1]);
                    float2 g2 = __bfloat1622float2(*(__nv_bfloat162*)&wv[2]);
                    float2 g3 = __bfloat1622float2(*(__nv_bfloat162*)&wv[3]);
                    const int d = c * 64 + ec * 8;
                    float4 fa = *(const float4*)(force + egrow + d);
                    float4 fb = *(const float4*)(force + egrow + d + 4);
                    float4 va = *(const float4*)(vsrc + egrow + d);
                    float4 vb = *(const float4*)(vsrc + egrow + d + 4);
                    float4 na, nb;
                    na.x = va.x + dcoef * (fa.x - g0.x);
                    na.y = va.y + dcoef * (fa.y - g0.y);
                    na.z = va.z + dcoef * (fa.z - g1.x);
                    na.w = va.w + dcoef * (fa.w - g1.y);
                    nb.x = vb.x + dcoef * (fb.x - g2.x);
                    nb.y = vb.y + dcoef * (fb.y - g2.y);
                    nb.z = vb.z + dcoef * (fb.z - g3.x);
                    nb.w = vb.w + dcoef * (fb.w - g3.y);
                    *(float4*)(g_vf + egrow + d)     = na;
                    *(float4*)(g_vf + egrow + d + 4) = nb;
                    wv[0] = bf2u(__float22bfloat162_rn(make_float2(na.x, na.y)));
                    wv[1] = bf2u(__float22bfloat162_rn(make_float2(na.z, na.w)));
                    wv[2] = bf2u(__float22bfloat162_rn(make_float2(nb.x, nb.y)));
                    wv[3] = bf2u(__float22bfloat162_rn(make_float2(nb.z, nb.w)));
                    sts128(gaddr, wv);
                    float4* oxa = (float4*)(out + egrow + d);
                    float4* oxb = (float4*)(out + egrow + d + 4);
                    if (step == 0) {
                        float4 ta, tb;
                        ta.x = K_C1f * va.x + K_C2f * na.x; ta.y = K_C1f * va.y + K_C2f * na.y;
                        ta.z = K_C1f * va.z + K_C2f * na.z; ta.w = K_C1f * va.w + K_C2f * na.w;
                        tb.x = K_C1f * vb.x + K_C2f * nb.x; tb.y = K_C1f * vb.y + K_C2f * nb.y;
                        tb.z = K_C1f * vb.z + K_C2f * nb.z; tb.w = K_C1f * vb.w + K_C2f * nb.w;
                        *oxa = ta; *oxb = tb;
                    } else if (step == 1) {
                        float4 ta = *oxa, tb = *oxb;
                        ta.x += K_C2f * na.x; ta.y += K_C2f * na.y;
                        ta.z += K_C2f * na.z; ta.w += K_C2f * na.w;
                        tb.x += K_C2f * nb.x; tb.y += K_C2f * nb.y;
                        tb.z += K_C2f * nb.z; tb.w += K_C2f * nb.w;
                        *oxa = ta; *oxb = tb;
                    } else {
                        float4 ta = *oxa, tb = *oxb;
                        float4 xa = *(const float4*)(x + egrow + d);
                        float4 xb = *(const float4*)(x + egrow + d + 4);
                        ta.x = xa.x + K_DT * (ta.x + K_C1f * na.x);
                        ta.y = xa.y + K_DT * (ta.y + K_C1f * na.y);
                        ta.z = xa.z + K_DT * (ta.z + K_C1f * na.z);
                        ta.w = xa.w + K_DT * (ta.w + K_C1f * na.w);
                        tb.x = xb.x + K_DT * (tb.x + K_C1f * nb.x);
                        tb.y = xb.y + K_DT * (tb.y + K_C1f * nb.y);
                        tb.z = xb.z + K_DT * (tb.z + K_C1f * nb.z);
                        tb.w = xb.w + K_DT * (tb.w + K_C1f * nb.w);
                        *oxa = ta; *oxb = tb;
                        *(float4*)(out + (size_t)BB * DD + egrow + d)     = na;
                        *(float4*)(out + (size_t)BB * DD + egrow + d + 4) = nb;
                    }
                }
                if (step < 2) nbar_arrive(6 + r, 512);    // SV tiles 4r..4r+3 hold vn(step)
            }
        }
    }
}

extern "C" void kernel_launch(void* const* d_in, const int* in_sizes, int n_in,
                              void* d_out, int out_size)
{
    const float* x     = (const float*)d_in[0];
    const float* v     = (const float*)d_in[1];
    const float* force = (const float*)d_in[2];
    const float* U     = (const float*)d_in[3];
    const float* W     = (const float*)d_in[4];
    float* out = (float*)d_out;

    const int smem_bytes = 214144;
    cudaFuncSetAttribute(yoshida_mma12_kernel, cudaFuncAttributeMaxDynamicSharedMemorySize, smem_bytes);

    prep_uw_kernel<<<1024, 256>>>(U, W);
    yoshida_mma12_kernel<<<NCTA, NTHR, smem_bytes>>>(x, v, force, out);
}